// round 1
// baseline (speedup 1.0000x reference)
#include <cuda_runtime.h>

// CovNet_3058016715001 — fused binarized-weight MLP
//   h   = clip(x @ sign(W1)^T + b1, -1, 1)     x:[8192,784] W1:[4096,784]
//   out = h @ W2^T + b2                        W2:[10,4096]  out:[8192,10]
//
// Strategy (round 0 baseline):
//   - single fused SGEMM kernel, 128x128 tile, BK=8, 8x8 per thread (256 thr)
//   - sign(W1) applied while staging into shared
//   - fc2 folded into epilogue: per-tile h @ W2^T partial (1.3% extra FLOPs),
//     reduced across the 16-thread column groups via warp shuffles,
//     accumulated into out with atomicAdd. out pre-seeded with b2 by init kernel.
//   - no h intermediate -> no 268 MB of extra HBM traffic, no second big kernel.

#define BATCH 8192
#define IN_F  784
#define HID   4096
#define NOUT  10

#define BM 128
#define BN 128
#define BK 8

__device__ __forceinline__ float sgnf(float w) {
    return (w > 0.0f) ? 1.0f : ((w < 0.0f) ? -1.0f : 0.0f);
}

__global__ void init_out_kernel(float* __restrict__ out, const float* __restrict__ b2) {
    int i = blockIdx.x * blockDim.x + threadIdx.x;
    if (i < BATCH * NOUT) {
        out[i] = b2[i % NOUT];
    }
}

__global__ void __launch_bounds__(256, 2) fused_mlp_kernel(
    const float* __restrict__ X,    // [BATCH, IN_F]
    const float* __restrict__ W1,   // [HID, IN_F]
    const float* __restrict__ b1,   // [HID]
    const float* __restrict__ W2,   // [NOUT, HID]
    float* __restrict__ out)        // [BATCH, NOUT], pre-seeded with b2
{
    __shared__ float As[BK][BM];    // x tile, transposed: As[k][m]
    __shared__ float Bs[BK][BN];    // sign(W1) tile, transposed: Bs[k][n]

    const int tid = threadIdx.x;
    const int tx  = tid & 15;       // 0..15  (column group)
    const int ty  = tid >> 4;       // 0..15  (row group)

    const int bm = blockIdx.y * BM; // batch-row base
    const int bn = blockIdx.x * BN; // hidden-col base

    // tile-load mapping: each thread loads one float4 of A and one of B
    const int lrow = tid >> 1;          // 0..127
    const int lcol = (tid & 1) * 4;     // 0 or 4

    const float* xp = X  + (size_t)(bm + lrow) * IN_F + lcol;
    const float* wp = W1 + (size_t)(bn + lrow) * IN_F + lcol;

    float acc[8][8];
    #pragma unroll
    for (int i = 0; i < 8; ++i)
        #pragma unroll
        for (int j = 0; j < 8; ++j)
            acc[i][j] = 0.0f;

    // ---- main loop over K = 784 (98 iters of BK=8) ----
    for (int k0 = 0; k0 < IN_F; k0 += BK) {
        float4 xa = *reinterpret_cast<const float4*>(xp + k0);
        float4 wa = *reinterpret_cast<const float4*>(wp + k0);

        As[lcol + 0][lrow] = xa.x;
        As[lcol + 1][lrow] = xa.y;
        As[lcol + 2][lrow] = xa.z;
        As[lcol + 3][lrow] = xa.w;

        Bs[lcol + 0][lrow] = sgnf(wa.x);
        Bs[lcol + 1][lrow] = sgnf(wa.y);
        Bs[lcol + 2][lrow] = sgnf(wa.z);
        Bs[lcol + 3][lrow] = sgnf(wa.w);

        __syncthreads();

        #pragma unroll
        for (int kk = 0; kk < BK; ++kk) {
            float a[8], b[8];
            #pragma unroll
            for (int i = 0; i < 8; ++i) a[i] = As[kk][ty * 8 + i];
            #pragma unroll
            for (int j = 0; j < 8; ++j) b[j] = Bs[kk][tx * 8 + j];
            #pragma unroll
            for (int i = 0; i < 8; ++i)
                #pragma unroll
                for (int j = 0; j < 8; ++j)
                    acc[i][j] = fmaf(a[i], b[j], acc[i][j]);
        }

        __syncthreads();
    }

    // ---- epilogue: bias + hardtanh in place ----
    float bj[8];
    #pragma unroll
    for (int j = 0; j < 8; ++j)
        bj[j] = b1[bn + tx * 8 + j];

    #pragma unroll
    for (int i = 0; i < 8; ++i)
        #pragma unroll
        for (int j = 0; j < 8; ++j)
            acc[i][j] = fminf(1.0f, fmaxf(-1.0f, acc[i][j] + bj[j]));

    // ---- fused fc2 partial: p[i] = sum_j h[i][j] * W2[o][bn + tx*8 + j] ----
    // Reduce across the 16-lane tx group (lanes 0-15 / 16-31 of each warp
    // share a ty, so xor-butterfly over {1,2,4,8} stays inside the group).
    #pragma unroll
    for (int o = 0; o < NOUT; ++o) {
        float w2j[8];
        const float* w2p = W2 + (size_t)o * HID + bn + tx * 8;
        #pragma unroll
        for (int j = 0; j < 8; ++j) w2j[j] = w2p[j];

        float p[8];
        #pragma unroll
        for (int i = 0; i < 8; ++i) {
            float s = 0.0f;
            #pragma unroll
            for (int j = 0; j < 8; ++j)
                s = fmaf(acc[i][j], w2j[j], s);
            p[i] = s;
        }

        #pragma unroll
        for (int i = 0; i < 8; ++i) {
            float v = p[i];
            v += __shfl_xor_sync(0xffffffffu, v, 1);
            v += __shfl_xor_sync(0xffffffffu, v, 2);
            v += __shfl_xor_sync(0xffffffffu, v, 4);
            v += __shfl_xor_sync(0xffffffffu, v, 8);
            if (tx == 0) {
                atomicAdd(&out[(size_t)(bm + ty * 8 + i) * NOUT + o], v);
            }
        }
    }
}

extern "C" void kernel_launch(void* const* d_in, const int* in_sizes, int n_in,
                              void* d_out, int out_size) {
    const float* X  = (const float*)d_in[0];   // [8192, 784]
    const float* W1 = (const float*)d_in[1];   // [4096, 784]
    const float* b1 = (const float*)d_in[2];   // [4096]
    const float* W2 = (const float*)d_in[3];   // [10, 4096]
    const float* b2 = (const float*)d_in[4];   // [10]
    float* out = (float*)d_out;                // [8192, 10]

    (void)in_sizes; (void)n_in; (void)out_size;

    // seed out with b2 (out is poisoned before timing)
    init_out_kernel<<<(BATCH * NOUT + 255) / 256, 256>>>(out, b2);

    dim3 grid(HID / BN, BATCH / BM);   // (32, 64) = 2048 blocks
    fused_mlp_kernel<<<grid, 256>>>(X, W1, b1, W2, out);
}

// round 2
// speedup vs baseline: 3.2376x; 3.2376x over previous
#include <cuda_runtime.h>
#include <cuda_bf16.h>
#include <cstdint>

// CovNet_3058016715001 — fused binarized-weight MLP, tensor-core round.
//   h   = clip(x @ sign(W1)^T + b1, -1, 1)     x:[8192,784] W1:[4096,784]
//   out = h @ W2^T + b2                        W2:[10,4096]  out:[8192,10]
//
// fc1 via bf16 mma.sync with hi/lo split of x (exact sign weights):
//   Xcat = [bf16(x) | bf16(x - bf16(x))]  -> K' = 2*800 (784 padded to 800)
//   single GEMM over K'=1600, B tile indexed mod 800.
// fc2 fused in epilogue (atomicAdd into out pre-seeded with b2).

#define BATCH 8192
#define IN_F  784
#define KP    800          // padded K per half (multiple of 32)
#define KCAT  1600         // 2*KP
#define HID   4096
#define NOUT  10

#define BM 128
#define BN 128
#define BK 32
#define LDS_PAD 40         // smem row stride in bf16 elems (80B: 16B-aligned, conflict-free)

__device__ __nv_bfloat16 g_Xcat[(size_t)BATCH * KCAT];   // 26.2 MB
__device__ __nv_bfloat16 g_Wb[(size_t)HID * KP];         // 6.55 MB

// ---------------------------------------------------------------- helpers
__device__ __forceinline__ uint32_t smem_u32(const void* p) {
    return (uint32_t)__cvta_generic_to_shared(p);
}

#define CP_ASYNC16(s, g) \
    asm volatile("cp.async.cg.shared.global [%0], [%1], 16;" :: "r"(s), "l"(g))
#define CP_COMMIT() asm volatile("cp.async.commit_group;")
#define CP_WAIT0()  asm volatile("cp.async.wait_group 0;" ::: "memory")

__device__ __forceinline__ void ldm_x4(uint32_t& r0, uint32_t& r1, uint32_t& r2,
                                       uint32_t& r3, uint32_t addr) {
    asm volatile("ldmatrix.sync.aligned.m8n8.x4.shared.b16 {%0,%1,%2,%3}, [%4];"
                 : "=r"(r0), "=r"(r1), "=r"(r2), "=r"(r3) : "r"(addr));
}

__device__ __forceinline__ void mma_bf16(float* d, const uint32_t* a, const uint32_t* b) {
    asm volatile(
        "mma.sync.aligned.m16n8k16.row.col.f32.bf16.bf16.f32 "
        "{%0,%1,%2,%3}, {%4,%5,%6,%7}, {%8,%9}, {%0,%1,%2,%3};"
        : "+f"(d[0]), "+f"(d[1]), "+f"(d[2]), "+f"(d[3])
        : "r"(a[0]), "r"(a[1]), "r"(a[2]), "r"(a[3]), "r"(b[0]), "r"(b[1]));
}

// ---------------------------------------------------------------- prep kernels
__global__ void init_out_kernel(float* __restrict__ out, const float* __restrict__ b2) {
    int i = blockIdx.x * blockDim.x + threadIdx.x;
    if (i < BATCH * NOUT) out[i] = b2[i % NOUT];
}

__global__ void conv_x_kernel(const float* __restrict__ X) {
    int idx = blockIdx.x * blockDim.x + threadIdx.x;
    if (idx >= BATCH * KCAT) return;
    int r = idx / KCAT, c = idx % KCAT;
    __nv_bfloat16 v = __float2bfloat16(0.0f);
    if (c < IN_F) {
        v = __float2bfloat16(X[(size_t)r * IN_F + c]);
    } else if (c >= KP && c < KP + IN_F) {
        float x = X[(size_t)r * IN_F + (c - KP)];
        __nv_bfloat16 hi = __float2bfloat16(x);
        v = __float2bfloat16(x - __bfloat162float(hi));
    }
    g_Xcat[idx] = v;
}

__global__ void conv_w_kernel(const float* __restrict__ W1) {
    int idx = blockIdx.x * blockDim.x + threadIdx.x;
    if (idx >= HID * KP) return;
    int r = idx / KP, c = idx % KP;
    float v = 0.0f;
    if (c < IN_F) {
        float w = W1[(size_t)r * IN_F + c];
        v = (w > 0.0f) ? 1.0f : ((w < 0.0f) ? -1.0f : 0.0f);
    }
    g_Wb[idx] = __float2bfloat16(v);
}

// ---------------------------------------------------------------- main GEMM
__global__ void __launch_bounds__(256, 2) fused_mma_kernel(
    const float* __restrict__ b1,
    const float* __restrict__ W2,
    float* __restrict__ out)
{
    __shared__ __nv_bfloat16 As[2][BM * LDS_PAD];   // 2 x 10240 B
    __shared__ __nv_bfloat16 Bs[2][BN * LDS_PAD];   // 2 x 10240 B
    __shared__ float W2s[NOUT][BN];                  // 5120 B
    __shared__ float b1s[BN];                        // 512 B

    const int tid  = threadIdx.x;
    const int lane = tid & 31;
    const int wid  = tid >> 5;
    const int wm   = wid & 3;        // 4 warps along M (32 rows each)
    const int wn   = wid >> 2;       // 2 warps along N (64 cols each)

    const int bm = blockIdx.y * BM;
    const int bn = blockIdx.x * BN;

    // ---- gmem->smem loader mapping: 2 x 16B per thread per tile ----
    int lr0 = tid >> 2;              // rows 0..63
    int lr1 = lr0 + 64;              // rows 64..127
    int lc  = (tid & 3) * 8;         // col elem 0/8/16/24

    const __nv_bfloat16* pX0 = g_Xcat + (size_t)(bm + lr0) * KCAT + lc;
    const __nv_bfloat16* pX1 = g_Xcat + (size_t)(bm + lr1) * KCAT + lc;
    const __nv_bfloat16* pW0 = g_Wb   + (size_t)(bn + lr0) * KP   + lc;
    const __nv_bfloat16* pW1 = g_Wb   + (size_t)(bn + lr1) * KP   + lc;

    const uint32_t sA0 = smem_u32(&As[0][0]);
    const uint32_t sB0 = smem_u32(&Bs[0][0]);
    const uint32_t STAGE = BM * LDS_PAD * 2;  // bytes per stage (10240)
    const uint32_t offA0 = (uint32_t)(lr0 * LDS_PAD + lc) * 2;
    const uint32_t offA1 = (uint32_t)(lr1 * LDS_PAD + lc) * 2;

    // ---- ldmatrix per-lane source offsets ----
    const int lg  = lane >> 3;       // 0..3 (8x8 matrix id)
    const int lr8 = lane & 7;
    // A: g0 rows+0 col+0 | g1 rows+8 col+0 | g2 rows+0 col+8 | g3 rows+8 col+8
    const int aRow = wm * 32 + ((lg & 1) << 3) + lr8;
    const int aCol = (lg >> 1) << 3;
    // B: g0 rows+0 col+0 | g1 rows+0 col+8 | g2 rows+8 col+0 | g3 rows+8 col+8
    const int bRow = wn * 64 + (((lane >> 4) & 1) << 3) + lr8;
    const int bCol = ((lg & 1) << 3);

    float acc[2][8][4];
    #pragma unroll
    for (int mi = 0; mi < 2; ++mi)
        #pragma unroll
        for (int ni = 0; ni < 8; ++ni)
            #pragma unroll
            for (int k = 0; k < 4; ++k) acc[mi][ni][k] = 0.0f;

    const int NT = KCAT / BK;        // 50 tiles

    // prologue: load tile 0 into stage 0
    {
        CP_ASYNC16(sA0 + offA0, pX0);
        CP_ASYNC16(sA0 + offA1, pX1);
        CP_ASYNC16(sB0 + offA0, pW0);
        CP_ASYNC16(sB0 + offA1, pW1);
        CP_COMMIT();
    }

    for (int t = 0; t < NT; ++t) {
        CP_WAIT0();
        __syncthreads();

        if (t + 1 < NT) {
            const int k0 = (t + 1) * BK;
            const int kb = (k0 < KP) ? k0 : (k0 - KP);
            const uint32_t st = ((t + 1) & 1) * STAGE;
            CP_ASYNC16(sA0 + st + offA0, pX0 + k0);
            CP_ASYNC16(sA0 + st + offA1, pX1 + k0);
            CP_ASYNC16(sB0 + st + offA0, pW0 + kb);
            CP_ASYNC16(sB0 + st + offA1, pW1 + kb);
            CP_COMMIT();
        }

        const uint32_t sA = sA0 + (t & 1) * STAGE;
        const uint32_t sB = sB0 + (t & 1) * STAGE;

        #pragma unroll
        for (int ks = 0; ks < 2; ++ks) {
            uint32_t a[2][4];
            #pragma unroll
            for (int mi = 0; mi < 2; ++mi) {
                uint32_t addr = sA + (uint32_t)(((aRow + mi * 16) * LDS_PAD) + ks * 16 + aCol) * 2;
                ldm_x4(a[mi][0], a[mi][1], a[mi][2], a[mi][3], addr);
            }
            uint32_t b[8][2];
            #pragma unroll
            for (int n2 = 0; n2 < 4; ++n2) {
                uint32_t addr = sB + (uint32_t)(((bRow + n2 * 16) * LDS_PAD) + ks * 16 + bCol) * 2;
                ldm_x4(b[2 * n2][0], b[2 * n2][1], b[2 * n2 + 1][0], b[2 * n2 + 1][1], addr);
            }
            #pragma unroll
            for (int mi = 0; mi < 2; ++mi)
                #pragma unroll
                for (int ni = 0; ni < 8; ++ni)
                    mma_bf16(acc[mi][ni], a[mi], b[ni]);
        }
    }

    // ---- stage W2 slice + b1 slice ----
    __syncthreads();
    for (int i = tid; i < NOUT * BN; i += 256) {
        int o = i / BN, n = i % BN;
        W2s[o][n] = W2[(size_t)o * HID + bn + n];
    }
    if (tid < BN) b1s[tid] = b1[bn + tid];
    __syncthreads();

    // ---- epilogue: bias + hardtanh, then fused fc2 ----
    const int dg = lane >> 2;        // row within 8
    const int dt = lane & 3;         // col pair selector

    #pragma unroll
    for (int mi = 0; mi < 2; ++mi)
        #pragma unroll
        for (int ni = 0; ni < 8; ++ni) {
            int nl0 = wn * 64 + ni * 8 + 2 * dt;
            float bb0 = b1s[nl0], bb1 = b1s[nl0 + 1];
            acc[mi][ni][0] = fminf(1.0f, fmaxf(-1.0f, acc[mi][ni][0] + bb0));
            acc[mi][ni][1] = fminf(1.0f, fmaxf(-1.0f, acc[mi][ni][1] + bb1));
            acc[mi][ni][2] = fminf(1.0f, fmaxf(-1.0f, acc[mi][ni][2] + bb0));
            acc[mi][ni][3] = fminf(1.0f, fmaxf(-1.0f, acc[mi][ni][3] + bb1));
        }

    #pragma unroll
    for (int o = 0; o < NOUT; ++o) {
        #pragma unroll
        for (int mi = 0; mi < 2; ++mi) {
            float sA_ = 0.0f, sB_ = 0.0f;
            #pragma unroll
            for (int ni = 0; ni < 8; ++ni) {
                int nl = wn * 64 + ni * 8 + 2 * dt;
                float w0 = W2s[o][nl], w1 = W2s[o][nl + 1];
                sA_ = fmaf(acc[mi][ni][0], w0, fmaf(acc[mi][ni][1], w1, sA_));
                sB_ = fmaf(acc[mi][ni][2], w0, fmaf(acc[mi][ni][3], w1, sB_));
            }
            // reduce across the 4-lane dt group
            sA_ += __shfl_xor_sync(0xffffffffu, sA_, 1);
            sA_ += __shfl_xor_sync(0xffffffffu, sA_, 2);
            sB_ += __shfl_xor_sync(0xffffffffu, sB_, 1);
            sB_ += __shfl_xor_sync(0xffffffffu, sB_, 2);
            if (dt == 0) {
                int rA = bm + wm * 32 + mi * 16 + dg;
                atomicAdd(&out[(size_t)rA * NOUT + o], sA_);
                atomicAdd(&out[(size_t)(rA + 8) * NOUT + o], sB_);
            }
        }
    }
}

// ---------------------------------------------------------------- launch
extern "C" void kernel_launch(void* const* d_in, const int* in_sizes, int n_in,
                              void* d_out, int out_size) {
    const float* X  = (const float*)d_in[0];   // [8192, 784]
    const float* W1 = (const float*)d_in[1];   // [4096, 784]
    const float* b1 = (const float*)d_in[2];   // [4096]
    const float* W2 = (const float*)d_in[3];   // [10, 4096]
    const float* b2 = (const float*)d_in[4];   // [10]
    float* out = (float*)d_out;                // [8192, 10]
    (void)in_sizes; (void)n_in; (void)out_size;

    init_out_kernel<<<(BATCH * NOUT + 255) / 256, 256>>>(out, b2);
    conv_x_kernel<<<(BATCH * KCAT + 255) / 256, 256>>>(X);
    conv_w_kernel<<<(HID * KP + 255) / 256, 256>>>(W1);

    dim3 grid(HID / BN, BATCH / BM);   // (32, 64)
    fused_mma_kernel<<<grid, 256>>>(b1, W2, out);
}

// round 5
// speedup vs baseline: 3.9470x; 1.2191x over previous
#include <cuda_runtime.h>
#include <cstdint>

// CovNet_3058016715001 — binarized-weight MLP via int8 dual-plane mma.sync.
//   h   = clip(x @ sign(W1)^T + b1, -1, 1)     x:[8192,784] W1:[4096,784]
//   out = h @ W2^T + b2                        W2:[10,4096]  out:[8192,10]
//
// x -> 16-bit fixed point Q = round(x*4096), split Q = 256*Qh + Ql (s8 planes).
// sign(W1) exact in s8. Two s32 GEMM accumulators (hi/lo plane), combined in
// epilogue: h = (256*accH + accL)/4096 + b1 -> clip -> fused fc2 -> atomicAdd.
// mma.sync.m16n8k32.s8 (sm_80 PTX: compiles for plain sm_100; tcgen05 does not).

#define BATCH 8192
#define IN_F  784
#define KP8   800           // K padded to 25 * 32
#define HID   4096
#define NOUT  10

#define BM 128
#define BN 128
#define NCH 25              // k-chunks of 32
#define NSTG 3
#define PLANE 4096          // one [128 rows x 32 B] tile
#define STAGE (3 * PLANE)   // A_hi, A_lo, B

#define SCALE_S 4096.0f
#define INV_S   (1.0f / 4096.0f)

static __device__ char g_Xh8[(size_t)BATCH * KP8];
static __device__ char g_Xl8[(size_t)BATCH * KP8];
static __device__ char g_W8 [(size_t)HID * KP8];

// ---------------------------------------------------------------- helpers
__device__ __forceinline__ uint32_t smem_u32(const void* p) {
    return (uint32_t)__cvta_generic_to_shared(p);
}

#define CP_ASYNC16(s, g) \
    asm volatile("cp.async.cg.shared.global [%0], [%1], 16;" :: "r"(s), "l"(g))
#define CP_COMMIT() asm volatile("cp.async.commit_group;")
#define CP_WAIT(n)  asm volatile("cp.async.wait_group %0;" :: "n"(n) : "memory")

__device__ __forceinline__ void ldm_x4(uint32_t& r0, uint32_t& r1, uint32_t& r2,
                                       uint32_t& r3, uint32_t addr) {
    asm volatile("ldmatrix.sync.aligned.m8n8.x4.shared.b16 {%0,%1,%2,%3}, [%4];"
                 : "=r"(r0), "=r"(r1), "=r"(r2), "=r"(r3) : "r"(addr));
}

#define MMA_S8(d, a, b) \
    asm volatile("mma.sync.aligned.m16n8k32.row.col.s32.s8.s8.s32 " \
        "{%0,%1,%2,%3}, {%4,%5,%6,%7}, {%8,%9}, {%0,%1,%2,%3};" \
        : "+r"((d)[0]), "+r"((d)[1]), "+r"((d)[2]), "+r"((d)[3]) \
        : "r"((a)[0]), "r"((a)[1]), "r"((a)[2]), "r"((a)[3]), \
          "r"((b)[0]), "r"((b)[1]))

__device__ __forceinline__ uint32_t sw128(uint32_t flat) {
    return flat ^ ((flat >> 3) & 0x70);
}

// ---------------------------------------------------------------- prep
__global__ void init_out_kernel(float* __restrict__ out, const float* __restrict__ b2) {
    int i = blockIdx.x * blockDim.x + threadIdx.x;
    if (i < BATCH * NOUT) out[i] = b2[i % NOUT];
}

__global__ void conv_x8_kernel(const float* __restrict__ X) {
    int idx = blockIdx.x * blockDim.x + threadIdx.x;   // BATCH * 200
    if (idx >= BATCH * (KP8 / 4)) return;
    int r  = idx / (KP8 / 4);
    int c4 = (idx % (KP8 / 4)) * 4;
    char hq[4], lq[4];
    #pragma unroll
    for (int j = 0; j < 4; ++j) {
        int col = c4 + j;
        float x = (col < IN_F) ? X[(size_t)r * IN_F + col] : 0.0f;
        int Q = __float2int_rn(x * SCALE_S);
        Q = max(-32512, min(32512, Q));
        int Qh = (Q + 128) >> 8;          // in [-127, 127]
        int Ql = Q - (Qh << 8);           // in [-128, 127]
        hq[j] = (char)Qh;
        lq[j] = (char)Ql;
    }
    *(char4*)(g_Xh8 + (size_t)r * KP8 + c4) = make_char4(hq[0], hq[1], hq[2], hq[3]);
    *(char4*)(g_Xl8 + (size_t)r * KP8 + c4) = make_char4(lq[0], lq[1], lq[2], lq[3]);
}

__global__ void conv_w8_kernel(const float* __restrict__ W1) {
    int idx = blockIdx.x * blockDim.x + threadIdx.x;   // HID * 200
    if (idx >= HID * (KP8 / 4)) return;
    int r  = idx / (KP8 / 4);
    int c4 = (idx % (KP8 / 4)) * 4;
    char s[4];
    #pragma unroll
    for (int j = 0; j < 4; ++j) {
        int col = c4 + j;
        char v = 0;
        if (col < IN_F) {
            float w = W1[(size_t)r * IN_F + col];
            v = (w > 0.0f) ? (char)1 : ((w < 0.0f) ? (char)-1 : (char)0);
        }
        s[j] = v;
    }
    *(char4*)(g_W8 + (size_t)r * KP8 + c4) = make_char4(s[0], s[1], s[2], s[3]);
}

// ---------------------------------------------------------------- main
__global__ void __launch_bounds__(512, 1) fused_i8_kernel(
    const float* __restrict__ b1, const float* __restrict__ W2,
    float* __restrict__ out)
{
    __shared__ __align__(128) char stg[NSTG][STAGE];   // 36864 B
    __shared__ float W2s[NOUT * BN];                    // 5120 B
    __shared__ float b1s[BN];                           // 512 B

    const int tid  = threadIdx.x;
    const int lane = tid & 31;
    const int wid  = tid >> 5;
    const int wm   = wid & 3;        // 4 warps along M (32 rows)
    const int wn   = wid >> 2;       // 4 warps along N (32 cols)

    const int bm = blockIdx.y * BM;
    const int bn = blockIdx.x * BN;

    // ---- stage W2 / b1 slices (read in epilogue only) ----
    for (int i = tid; i < NOUT * BN; i += 512)
        W2s[i] = W2[(size_t)(i >> 7) * HID + bn + (i & 127)];
    if (tid < BN) b1s[tid] = b1[bn + tid];

    // ---- loader mapping: 256 x 16B chunks per plane ----
    const int lc   = tid & 255;
    const int lrow = lc >> 1;
    const int lseg = lc & 1;
    const uint32_t lsw = sw128((uint32_t)(lrow * 32 + lseg * 16));
    const char* gA = ((tid < 256) ? g_Xh8 : g_Xl8)
                     + (size_t)(bm + lrow) * KP8 + lseg * 16;
    const char* gB = g_W8 + (size_t)(bn + lrow) * KP8 + lseg * 16;
    const uint32_t planeA = (tid < 256) ? 0u : (uint32_t)PLANE;
    const uint32_t stgBase = smem_u32(&stg[0][0]);

    // ---- ldmatrix per-lane swizzled offsets ----
    const int lg  = lane >> 3;
    const int lr8 = lane & 7;
    uint32_t aOff[2], bOff[2];
    #pragma unroll
    for (int mi = 0; mi < 2; ++mi) {
        int r = wm * 32 + mi * 16 + ((lg & 1) << 3) + lr8;
        aOff[mi] = sw128((uint32_t)(r * 32 + (lg >> 1) * 16));
    }
    #pragma unroll
    for (int n2 = 0; n2 < 2; ++n2) {
        int r = wn * 32 + n2 * 16 + (((lane >> 4) & 1) << 3) + lr8;
        bOff[n2] = sw128((uint32_t)(r * 32 + (lg & 1) * 16));
    }

    int accH[2][4][4], accL[2][4][4];
    #pragma unroll
    for (int mi = 0; mi < 2; ++mi)
        #pragma unroll
        for (int ni = 0; ni < 4; ++ni)
            #pragma unroll
            for (int q = 0; q < 4; ++q) { accH[mi][ni][q] = 0; accL[mi][ni][q] = 0; }

    // ---- pipeline ----
    // preload chunks 0, 1
    #pragma unroll
    for (int p = 0; p < 2; ++p) {
        uint32_t dst = stgBase + p * STAGE;
        CP_ASYNC16(dst + planeA + lsw, gA + p * 32);
        if (tid < 256) CP_ASYNC16(dst + 2 * PLANE + lsw, gB + p * 32);
        CP_COMMIT();
    }

    for (int kc = 0; kc < NCH; ++kc) {
        const int s = kc % NSTG;
        if (kc >= NCH - 1) { CP_WAIT(0); } else { CP_WAIT(1); }
        __syncthreads();

        if (kc + 2 < NCH) {
            uint32_t dst = stgBase + ((kc + 2) % NSTG) * STAGE;
            CP_ASYNC16(dst + planeA + lsw, gA + (kc + 2) * 32);
            if (tid < 256) CP_ASYNC16(dst + 2 * PLANE + lsw, gB + (kc + 2) * 32);
            CP_COMMIT();
        }

        const uint32_t base = stgBase + s * STAGE;
        uint32_t ah[2][4], al[2][4], bb[4][2];
        #pragma unroll
        for (int mi = 0; mi < 2; ++mi)
            ldm_x4(ah[mi][0], ah[mi][1], ah[mi][2], ah[mi][3], base + aOff[mi]);
        #pragma unroll
        for (int mi = 0; mi < 2; ++mi)
            ldm_x4(al[mi][0], al[mi][1], al[mi][2], al[mi][3], base + PLANE + aOff[mi]);
        #pragma unroll
        for (int n2 = 0; n2 < 2; ++n2)
            ldm_x4(bb[2 * n2][0], bb[2 * n2][1], bb[2 * n2 + 1][0], bb[2 * n2 + 1][1],
                   base + 2 * PLANE + bOff[n2]);

        #pragma unroll
        for (int mi = 0; mi < 2; ++mi)
            #pragma unroll
            for (int ni = 0; ni < 4; ++ni) {
                MMA_S8(accH[mi][ni], ah[mi], bb[ni]);
                MMA_S8(accL[mi][ni], al[mi], bb[ni]);
            }
    }

    // ---- epilogue: combine planes, bias + hardtanh, fused fc2 ----
    const int dg = lane >> 2;
    const int dt = lane & 3;

    float hv[2][4][4];
    #pragma unroll
    for (int mi = 0; mi < 2; ++mi)
        #pragma unroll
        for (int ni = 0; ni < 4; ++ni)
            #pragma unroll
            for (int q = 0; q < 4; ++q) {
                int n = wn * 32 + ni * 8 + 2 * dt + (q & 1);
                float hf = fmaf(256.0f, (float)accH[mi][ni][q], (float)accL[mi][ni][q]);
                float v  = fmaf(hf, INV_S, b1s[n]);
                hv[mi][ni][q] = fminf(1.0f, fmaxf(-1.0f, v));
            }

    #pragma unroll
    for (int o = 0; o < NOUT; ++o) {
        #pragma unroll
        for (int mi = 0; mi < 2; ++mi) {
            float s0 = 0.0f, s1 = 0.0f;
            #pragma unroll
            for (int ni = 0; ni < 4; ++ni) {
                int n0 = wn * 32 + ni * 8 + 2 * dt;
                float w0 = W2s[o * BN + n0];
                float w1 = W2s[o * BN + n0 + 1];
                s0 = fmaf(hv[mi][ni][0], w0, fmaf(hv[mi][ni][1], w1, s0));
                s1 = fmaf(hv[mi][ni][2], w0, fmaf(hv[mi][ni][3], w1, s1));
            }
            s0 += __shfl_xor_sync(0xffffffffu, s0, 1);
            s0 += __shfl_xor_sync(0xffffffffu, s0, 2);
            s1 += __shfl_xor_sync(0xffffffffu, s1, 1);
            s1 += __shfl_xor_sync(0xffffffffu, s1, 2);
            if (dt == 0) {
                int r0 = bm + wm * 32 + mi * 16 + dg;
                atomicAdd(&out[(size_t)r0 * NOUT + o], s0);
                atomicAdd(&out[(size_t)(r0 + 8) * NOUT + o], s1);
            }
        }
    }
}

// ---------------------------------------------------------------- launch
extern "C" void kernel_launch(void* const* d_in, const int* in_sizes, int n_in,
                              void* d_out, int out_size) {
    const float* X  = (const float*)d_in[0];   // [8192, 784]
    const float* W1 = (const float*)d_in[1];   // [4096, 784]
    const float* b1 = (const float*)d_in[2];   // [4096]
    const float* W2 = (const float*)d_in[3];   // [10, 4096]
    const float* b2 = (const float*)d_in[4];   // [10]
    float* out = (float*)d_out;                // [8192, 10]
    (void)in_sizes; (void)n_in; (void)out_size;

    init_out_kernel<<<(BATCH * NOUT + 255) / 256, 256>>>(out, b2);
    conv_x8_kernel<<<(BATCH * (KP8 / 4) + 255) / 256, 256>>>(X);
    conv_w8_kernel<<<(HID * (KP8 / 4) + 255) / 256, 256>>>(W1);

    dim3 grid(HID / BN, BATCH / BM);   // (32, 64) = 2048 CTAs
    fused_i8_kernel<<<grid, 512>>>(b1, W2, out);
}

// round 6
// speedup vs baseline: 4.2785x; 1.0840x over previous
#include <cuda_runtime.h>
#include <cstdint>

// CovNet_3058016715001 — binarized-weight MLP via int8 dual-plane mma.sync.
// Round 6: BK=64 (13 barriers instead of 25), 3-stage cp.async pipeline.
//   h   = clip(x @ sign(W1)^T + b1, -1, 1)     x:[8192,784] W1:[4096,784]
//   out = h @ W2^T + b2                        W2:[10,4096]  out:[8192,10]
//
// x -> Q = round(x*4096) = 256*Qh + Ql (two s8 planes); sign(W1) exact s8.
// Two s32 accumulator sets; epilogue: h = (256*accH + accL)/4096 + b1
// -> clip -> fused fc2 -> atomicAdd(out pre-seeded with b2).

#define BATCH 8192
#define IN_F  784
#define KP8   832           // K padded to 13 * 64
#define HID   4096
#define NOUT  10

#define BM 128
#define BN 128
#define BK 64
#define NCH 13              // KP8 / BK
#define NSTG 3
#define PLANE 8192          // one [128 rows x 64 B] tile
#define STAGE (3 * PLANE)   // A_hi, A_lo, B  = 24576 B

// dynamic smem map (128-aligned base):
//   [0, 73728)       3 stages
//   [73728, 78848)   W2s [10][128] f32
//   [78848, 79360)   b1s [128] f32
#define OFF_W2   73728
#define OFF_B1   78848
#define SMEM_REQ (79360 + 128)

#define SCALE_S 4096.0f
#define INV_S   (1.0f / 4096.0f)

static __device__ char g_Xh8[(size_t)BATCH * KP8];
static __device__ char g_Xl8[(size_t)BATCH * KP8];
static __device__ char g_W8 [(size_t)HID * KP8];

// ---------------------------------------------------------------- helpers
__device__ __forceinline__ uint32_t smem_u32(const void* p) {
    return (uint32_t)__cvta_generic_to_shared(p);
}

#define CP_ASYNC16(s, g) \
    asm volatile("cp.async.cg.shared.global [%0], [%1], 16;" :: "r"(s), "l"(g))
#define CP_COMMIT() asm volatile("cp.async.commit_group;")
#define CP_WAIT(n)  asm volatile("cp.async.wait_group %0;" :: "n"(n) : "memory")

__device__ __forceinline__ void ldm_x4(uint32_t& r0, uint32_t& r1, uint32_t& r2,
                                       uint32_t& r3, uint32_t addr) {
    asm volatile("ldmatrix.sync.aligned.m8n8.x4.shared.b16 {%0,%1,%2,%3}, [%4];"
                 : "=r"(r0), "=r"(r1), "=r"(r2), "=r"(r3) : "r"(addr));
}

#define MMA_S8(d, a, b) \
    asm volatile("mma.sync.aligned.m16n8k32.row.col.s32.s8.s8.s32 " \
        "{%0,%1,%2,%3}, {%4,%5,%6,%7}, {%8,%9}, {%0,%1,%2,%3};" \
        : "+r"((d)[0]), "+r"((d)[1]), "+r"((d)[2]), "+r"((d)[3]) \
        : "r"((a)[0]), "r"((a)[1]), "r"((a)[2]), "r"((a)[3]), \
          "r"((b)[0]), "r"((b)[1]))

__device__ __forceinline__ uint32_t sw128(uint32_t flat) {
    return flat ^ ((flat >> 3) & 0x70);
}

// ---------------------------------------------------------------- prep
__global__ void init_out_kernel(float* __restrict__ out, const float* __restrict__ b2) {
    int i = blockIdx.x * blockDim.x + threadIdx.x;
    if (i < BATCH * NOUT) out[i] = b2[i % NOUT];
}

__global__ void conv_x8_kernel(const float* __restrict__ X) {
    int idx = blockIdx.x * blockDim.x + threadIdx.x;
    if (idx >= BATCH * (KP8 / 4)) return;
    int r  = idx / (KP8 / 4);
    int c4 = (idx % (KP8 / 4)) * 4;
    char hq[4], lq[4];
    #pragma unroll
    for (int j = 0; j < 4; ++j) {
        int col = c4 + j;
        float x = (col < IN_F) ? X[(size_t)r * IN_F + col] : 0.0f;
        int Q = __float2int_rn(x * SCALE_S);
        Q = max(-32512, min(32512, Q));
        int Qh = (Q + 128) >> 8;
        int Ql = Q - (Qh << 8);
        hq[j] = (char)Qh;
        lq[j] = (char)Ql;
    }
    *(char4*)(g_Xh8 + (size_t)r * KP8 + c4) = make_char4(hq[0], hq[1], hq[2], hq[3]);
    *(char4*)(g_Xl8 + (size_t)r * KP8 + c4) = make_char4(lq[0], lq[1], lq[2], lq[3]);
}

__global__ void conv_w8_kernel(const float* __restrict__ W1) {
    int idx = blockIdx.x * blockDim.x + threadIdx.x;
    if (idx >= HID * (KP8 / 4)) return;
    int r  = idx / (KP8 / 4);
    int c4 = (idx % (KP8 / 4)) * 4;
    char s[4];
    #pragma unroll
    for (int j = 0; j < 4; ++j) {
        int col = c4 + j;
        char v = 0;
        if (col < IN_F) {
            float w = W1[(size_t)r * IN_F + col];
            v = (w > 0.0f) ? (char)1 : ((w < 0.0f) ? (char)-1 : (char)0);
        }
        s[j] = v;
    }
    *(char4*)(g_W8 + (size_t)r * KP8 + c4) = make_char4(s[0], s[1], s[2], s[3]);
}

// ---------------------------------------------------------------- main
__global__ void __launch_bounds__(512, 1) fused_i8_kernel(
    const float* __restrict__ b1, const float* __restrict__ W2,
    float* __restrict__ out)
{
    extern __shared__ char smem_raw[];
    const uint32_t rawA  = smem_u32(smem_raw);
    const uint32_t sbase = (rawA + 127) & ~127u;
    char* gbase = smem_raw + (sbase - rawA);
    float* W2s = (float*)(gbase + OFF_W2);
    float* b1s = (float*)(gbase + OFF_B1);

    const int tid  = threadIdx.x;
    const int lane = tid & 31;
    const int wid  = tid >> 5;
    const int wm   = wid & 3;        // 4 warps along M (32 rows)
    const int wn   = wid >> 2;       // 4 warps along N (32 cols)

    const int bm = blockIdx.y * BM;
    const int bn = blockIdx.x * BN;

    // ---- stage W2 / b1 slices (used only in epilogue) ----
    for (int i = tid; i < NOUT * BN; i += 512)
        W2s[i] = W2[(size_t)(i >> 7) * HID + bn + (i & 127)];
    if (tid < BN) b1s[tid] = b1[bn + tid];

    // ---- loader mapping: each thread moves one 16B chunk per plane ----
    const int lrow = tid >> 2;           // 0..127
    const int lseg = tid & 3;            // 16B segment within 64B row
    const uint32_t lsw = sw128((uint32_t)tid * 16);
    const char* gXh = g_Xh8 + (size_t)(bm + lrow) * KP8 + lseg * 16;
    const char* gXl = g_Xl8 + (size_t)(bm + lrow) * KP8 + lseg * 16;
    const char* gW  = g_W8  + (size_t)(bn + lrow) * KP8 + lseg * 16;

    // ---- ldmatrix per-lane swizzled offsets (row stride 64 B, 2 k-steps) ----
    const int lg  = lane >> 3;
    const int lr8 = lane & 7;
    uint32_t aOff[2][2], bOff[2][2];
    #pragma unroll
    for (int mi = 0; mi < 2; ++mi) {
        int r = wm * 32 + mi * 16 + ((lg & 1) << 3) + lr8;
        #pragma unroll
        for (int ks = 0; ks < 2; ++ks)
            aOff[mi][ks] = sw128((uint32_t)(r * 64 + ks * 32 + (lg >> 1) * 16));
    }
    #pragma unroll
    for (int n2 = 0; n2 < 2; ++n2) {
        int r = wn * 32 + n2 * 16 + (((lane >> 4) & 1) << 3) + lr8;
        #pragma unroll
        for (int ks = 0; ks < 2; ++ks)
            bOff[n2][ks] = sw128((uint32_t)(r * 64 + ks * 32 + (lg & 1) * 16));
    }

    int accH[2][4][4], accL[2][4][4];
    #pragma unroll
    for (int mi = 0; mi < 2; ++mi)
        #pragma unroll
        for (int ni = 0; ni < 4; ++ni)
            #pragma unroll
            for (int q = 0; q < 4; ++q) { accH[mi][ni][q] = 0; accL[mi][ni][q] = 0; }

    // ---- preload chunks 0, 1 ----
    #pragma unroll
    for (int p = 0; p < 2; ++p) {
        uint32_t dst = sbase + p * STAGE;
        CP_ASYNC16(dst + 0 * PLANE + lsw, gXh + p * BK);
        CP_ASYNC16(dst + 1 * PLANE + lsw, gXl + p * BK);
        CP_ASYNC16(dst + 2 * PLANE + lsw, gW  + p * BK);
        CP_COMMIT();
    }

    for (int kc = 0; kc < NCH; ++kc) {
        const int s = kc % NSTG;
        if (kc == NCH - 1) { CP_WAIT(0); } else { CP_WAIT(1); }
        __syncthreads();

        if (kc + 2 < NCH) {
            uint32_t dst = sbase + ((kc + 2) % NSTG) * STAGE;
            CP_ASYNC16(dst + 0 * PLANE + lsw, gXh + (kc + 2) * BK);
            CP_ASYNC16(dst + 1 * PLANE + lsw, gXl + (kc + 2) * BK);
            CP_ASYNC16(dst + 2 * PLANE + lsw, gW  + (kc + 2) * BK);
            CP_COMMIT();
        }

        const uint32_t base = sbase + s * STAGE;
        #pragma unroll
        for (int ks = 0; ks < 2; ++ks) {
            uint32_t ah[2][4], al[2][4], bb[4][2];
            #pragma unroll
            for (int n2 = 0; n2 < 2; ++n2)
                ldm_x4(bb[2 * n2][0], bb[2 * n2][1], bb[2 * n2 + 1][0], bb[2 * n2 + 1][1],
                       base + 2 * PLANE + bOff[n2][ks]);
            #pragma unroll
            for (int mi = 0; mi < 2; ++mi)
                ldm_x4(ah[mi][0], ah[mi][1], ah[mi][2], ah[mi][3],
                       base + aOff[mi][ks]);
            #pragma unroll
            for (int mi = 0; mi < 2; ++mi)
                ldm_x4(al[mi][0], al[mi][1], al[mi][2], al[mi][3],
                       base + PLANE + aOff[mi][ks]);

            #pragma unroll
            for (int mi = 0; mi < 2; ++mi)
                #pragma unroll
                for (int ni = 0; ni < 4; ++ni) {
                    MMA_S8(accH[mi][ni], ah[mi], bb[ni]);
                    MMA_S8(accL[mi][ni], al[mi], bb[ni]);
                }
        }
    }

    // ---- epilogue: combine planes, bias + hardtanh, fused fc2 ----
    const int dg = lane >> 2;
    const int dt = lane & 3;

    float hv[2][4][4];
    #pragma unroll
    for (int mi = 0; mi < 2; ++mi)
        #pragma unroll
        for (int ni = 0; ni < 4; ++ni)
            #pragma unroll
            for (int q = 0; q < 4; ++q) {
                int n = wn * 32 + ni * 8 + 2 * dt + (q & 1);
                float hf = fmaf(256.0f, (float)accH[mi][ni][q], (float)accL[mi][ni][q]);
                float v  = fmaf(hf, INV_S, b1s[n]);
                hv[mi][ni][q] = fminf(1.0f, fmaxf(-1.0f, v));
            }

    #pragma unroll
    for (int o = 0; o < NOUT; ++o) {
        #pragma unroll
        for (int mi = 0; mi < 2; ++mi) {
            float s0 = 0.0f, s1 = 0.0f;
            #pragma unroll
            for (int ni = 0; ni < 4; ++ni) {
                int n0 = wn * 32 + ni * 8 + 2 * dt;
                float w0 = W2s[o * BN + n0];
                float w1 = W2s[o * BN + n0 + 1];
                s0 = fmaf(hv[mi][ni][0], w0, fmaf(hv[mi][ni][1], w1, s0));
                s1 = fmaf(hv[mi][ni][2], w0, fmaf(hv[mi][ni][3], w1, s1));
            }
            s0 += __shfl_xor_sync(0xffffffffu, s0, 1);
            s0 += __shfl_xor_sync(0xffffffffu, s0, 2);
            s1 += __shfl_xor_sync(0xffffffffu, s1, 1);
            s1 += __shfl_xor_sync(0xffffffffu, s1, 2);
            if (dt == 0) {
                int r0 = bm + wm * 32 + mi * 16 + dg;
                atomicAdd(&out[(size_t)r0 * NOUT + o], s0);
                atomicAdd(&out[(size_t)(r0 + 8) * NOUT + o], s1);
            }
        }
    }
}

// ---------------------------------------------------------------- launch
extern "C" void kernel_launch(void* const* d_in, const int* in_sizes, int n_in,
                              void* d_out, int out_size) {
    const float* X  = (const float*)d_in[0];   // [8192, 784]
    const float* W1 = (const float*)d_in[1];   // [4096, 784]
    const float* b1 = (const float*)d_in[2];   // [4096]
    const float* W2 = (const float*)d_in[3];   // [10, 4096]
    const float* b2 = (const float*)d_in[4];   // [10]
    float* out = (float*)d_out;                // [8192, 10]
    (void)in_sizes; (void)n_in; (void)out_size;

    // Unconditional (no static guards); attribute-set is not a stream op and
    // is safe under graph capture.
    cudaFuncSetAttribute(fused_i8_kernel,
                         cudaFuncAttributeMaxDynamicSharedMemorySize, SMEM_REQ);

    init_out_kernel<<<(BATCH * NOUT + 255) / 256, 256>>>(out, b2);
    conv_x8_kernel<<<(BATCH * (KP8 / 4) + 255) / 256, 256>>>(X);
    conv_w8_kernel<<<(HID * (KP8 / 4) + 255) / 256, 256>>>(W1);

    dim3 grid(HID / BN, BATCH / BM);   // (32, 64) = 2048 CTAs
    fused_i8_kernel<<<grid, 512, SMEM_REQ>>>(b1, W2, out);
}

// round 7
// speedup vs baseline: 4.5740x; 1.0691x over previous
#include <cuda_runtime.h>
#include <cstdint>

// CovNet_3058016715001 — binarized-weight MLP via int8 dual-plane mma.sync.
// Round 7: 2 CTAs/SM (256 thr, BM=64 BN=128), NSTG=4, wait_group 2.
//   h   = clip(x @ sign(W1)^T + b1, -1, 1)     x:[8192,784] W1:[4096,784]
//   out = h @ W2^T + b2                        W2:[10,4096]  out:[8192,10]
//
// x -> Q = round(x*4096) = 256*Qh + Ql (two s8 planes); sign(W1) exact s8.
// Dual s32 accumulators; epilogue h = (256*accH + accL)/4096 + b1 -> clip
// -> fused fc2 -> atomicAdd (out pre-seeded with b2).

#define BATCH 8192
#define IN_F  784
#define KP8   832           // 13 * 64
#define HID   4096
#define NOUT  10

#define BM 64
#define BN 128
#define BK 64
#define NCH 13
#define NSTG 4
#define PLANE_A 4096        // [64 rows x 64 B]
#define OFF_ALO 4096
#define OFF_BW  8192
#define STAGE   16384       // Ahi(4K) Alo(4K) B(8K)

// dynamic smem map (128-aligned base):
//   [0, 65536)       4 stages
//   [65536, 70656)   W2s [10][128] f32
//   [70656, 71168)   b1s [128] f32
#define OFF_W2   65536
#define OFF_B1   70656
#define SMEM_REQ (71168 + 128)

#define SCALE_S 4096.0f
#define INV_S   (1.0f / 4096.0f)

static __device__ char g_Xh8[(size_t)BATCH * KP8];
static __device__ char g_Xl8[(size_t)BATCH * KP8];
static __device__ char g_W8 [(size_t)HID * KP8];

// ---------------------------------------------------------------- helpers
__device__ __forceinline__ uint32_t smem_u32(const void* p) {
    return (uint32_t)__cvta_generic_to_shared(p);
}

#define CP_ASYNC16(s, g) \
    asm volatile("cp.async.cg.shared.global [%0], [%1], 16;" :: "r"(s), "l"(g))
#define CP_COMMIT() asm volatile("cp.async.commit_group;")
#define CP_WAIT(n)  asm volatile("cp.async.wait_group %0;" :: "n"(n) : "memory")

__device__ __forceinline__ void ldm_x4(uint32_t& r0, uint32_t& r1, uint32_t& r2,
                                       uint32_t& r3, uint32_t addr) {
    asm volatile("ldmatrix.sync.aligned.m8n8.x4.shared.b16 {%0,%1,%2,%3}, [%4];"
                 : "=r"(r0), "=r"(r1), "=r"(r2), "=r"(r3) : "r"(addr));
}

#define MMA_S8(d, a, b) \
    asm volatile("mma.sync.aligned.m16n8k32.row.col.s32.s8.s8.s32 " \
        "{%0,%1,%2,%3}, {%4,%5,%6,%7}, {%8,%9}, {%0,%1,%2,%3};" \
        : "+r"((d)[0]), "+r"((d)[1]), "+r"((d)[2]), "+r"((d)[3]) \
        : "r"((a)[0]), "r"((a)[1]), "r"((a)[2]), "r"((a)[3]), \
          "r"((b)[0]), "r"((b)[1]))

// bijective smem scramble (consistent between cp.async writes and ldmatrix reads)
__device__ __forceinline__ uint32_t sw128(uint32_t flat) {
    return flat ^ ((flat >> 3) & 0x70);
}

// ---------------------------------------------------------------- prep
__global__ void init_out_kernel(float* __restrict__ out, const float* __restrict__ b2) {
    int i = blockIdx.x * blockDim.x + threadIdx.x;
    if (i < BATCH * NOUT) out[i] = b2[i % NOUT];
}

__global__ void conv_x8_kernel(const float* __restrict__ X) {
    int idx = blockIdx.x * blockDim.x + threadIdx.x;
    if (idx >= BATCH * (KP8 / 4)) return;
    int r  = idx / (KP8 / 4);
    int c4 = (idx % (KP8 / 4)) * 4;
    char hq[4], lq[4];
    #pragma unroll
    for (int j = 0; j < 4; ++j) {
        int col = c4 + j;
        float x = (col < IN_F) ? X[(size_t)r * IN_F + col] : 0.0f;
        int Q = __float2int_rn(x * SCALE_S);
        Q = max(-32512, min(32512, Q));
        int Qh = (Q + 128) >> 8;
        int Ql = Q - (Qh << 8);
        hq[j] = (char)Qh;
        lq[j] = (char)Ql;
    }
    *(char4*)(g_Xh8 + (size_t)r * KP8 + c4) = make_char4(hq[0], hq[1], hq[2], hq[3]);
    *(char4*)(g_Xl8 + (size_t)r * KP8 + c4) = make_char4(lq[0], lq[1], lq[2], lq[3]);
}

__global__ void conv_w8_kernel(const float* __restrict__ W1) {
    int idx = blockIdx.x * blockDim.x + threadIdx.x;
    if (idx >= HID * (KP8 / 4)) return;
    int r  = idx / (KP8 / 4);
    int c4 = (idx % (KP8 / 4)) * 4;
    char s[4];
    #pragma unroll
    for (int j = 0; j < 4; ++j) {
        int col = c4 + j;
        char v = 0;
        if (col < IN_F) {
            float w = W1[(size_t)r * IN_F + col];
            v = (w > 0.0f) ? (char)1 : ((w < 0.0f) ? (char)-1 : (char)0);
        }
        s[j] = v;
    }
    *(char4*)(g_W8 + (size_t)r * KP8 + c4) = make_char4(s[0], s[1], s[2], s[3]);
}

// ---------------------------------------------------------------- main
__global__ void __launch_bounds__(256, 2) fused_i8_kernel(
    const float* __restrict__ b1, const float* __restrict__ W2,
    float* __restrict__ out)
{
    extern __shared__ char smem_raw[];
    const uint32_t rawA  = smem_u32(smem_raw);
    const uint32_t sbase = (rawA + 127) & ~127u;
    char* gbase = smem_raw + (sbase - rawA);
    float* W2s = (float*)(gbase + OFF_W2);
    float* b1s = (float*)(gbase + OFF_B1);

    const int tid  = threadIdx.x;
    const int lane = tid & 31;
    const int wid  = tid >> 5;
    const int wm   = wid & 1;        // 2 warps along M (32 rows each)
    const int wn   = wid >> 1;       // 4 warps along N (32 cols each)

    const int bm = blockIdx.y * BM;
    const int bn = blockIdx.x * BN;

    // ---- stage W2 / b1 slices (used only in epilogue) ----
    for (int i = tid; i < NOUT * BN; i += 256)
        W2s[i] = W2[(size_t)(i >> 7) * HID + bn + (i & 127)];
    if (tid < BN) b1s[tid] = b1[bn + tid];

    // ---- loader mapping ----
    // A planes: 64 rows x 4 segs = 256 chunks -> one per thread.
    // B plane: 128 rows x 4 segs = 512 chunks -> two per thread.
    const int lrow = tid >> 2;           // 0..63
    const int lseg = tid & 3;
    const uint32_t aSw  = sw128((uint32_t)tid * 16);
    const uint32_t bSw0 = aSw;                                  // rows 0..63
    const uint32_t bSw1 = sw128((uint32_t)tid * 16 + 4096);     // rows 64..127
    const char* gXh = g_Xh8 + (size_t)(bm + lrow) * KP8 + lseg * 16;
    const char* gXl = g_Xl8 + (size_t)(bm + lrow) * KP8 + lseg * 16;
    const char* gW0 = g_W8  + (size_t)(bn + lrow) * KP8 + lseg * 16;
    const char* gW1 = g_W8  + (size_t)(bn + 64 + lrow) * KP8 + lseg * 16;

    // ---- ldmatrix per-lane offsets (row stride 64 B, 2 k-steps) ----
    const int lg  = lane >> 3;
    const int lr8 = lane & 7;
    uint32_t aOff[2][2], bOff[2][2];
    #pragma unroll
    for (int mi = 0; mi < 2; ++mi) {
        int r = wm * 32 + mi * 16 + ((lg & 1) << 3) + lr8;
        #pragma unroll
        for (int ks = 0; ks < 2; ++ks)
            aOff[mi][ks] = sw128((uint32_t)(r * 64 + ks * 32 + (lg >> 1) * 16));
    }
    #pragma unroll
    for (int n2 = 0; n2 < 2; ++n2) {
        int r = wn * 32 + n2 * 16 + (((lane >> 4) & 1) << 3) + lr8;
        #pragma unroll
        for (int ks = 0; ks < 2; ++ks)
            bOff[n2][ks] = sw128((uint32_t)(r * 64 + ks * 32 + (lg & 1) * 16));
    }

    int accH[2][4][4], accL[2][4][4];
    #pragma unroll
    for (int mi = 0; mi < 2; ++mi)
        #pragma unroll
        for (int ni = 0; ni < 4; ++ni)
            #pragma unroll
            for (int q = 0; q < 4; ++q) { accH[mi][ni][q] = 0; accL[mi][ni][q] = 0; }

    // ---- preload chunks 0..2 ----
    #pragma unroll
    for (int p = 0; p < 3; ++p) {
        uint32_t dst = sbase + p * STAGE;
        CP_ASYNC16(dst + aSw, gXh + p * BK);
        CP_ASYNC16(dst + OFF_ALO + aSw, gXl + p * BK);
        CP_ASYNC16(dst + OFF_BW + bSw0, gW0 + p * BK);
        CP_ASYNC16(dst + OFF_BW + bSw1, gW1 + p * BK);
        CP_COMMIT();
    }

    for (int kc = 0; kc < NCH; ++kc) {
        const int s = kc & 3;
        if (kc < NCH - 2)       { CP_WAIT(2); }
        else if (kc == NCH - 2) { CP_WAIT(1); }
        else                    { CP_WAIT(0); }
        __syncthreads();

        if (kc + 3 < NCH) {
            uint32_t dst = sbase + ((kc + 3) & 3) * STAGE;
            CP_ASYNC16(dst + aSw, gXh + (kc + 3) * BK);
            CP_ASYNC16(dst + OFF_ALO + aSw, gXl + (kc + 3) * BK);
            CP_ASYNC16(dst + OFF_BW + bSw0, gW0 + (kc + 3) * BK);
            CP_ASYNC16(dst + OFF_BW + bSw1, gW1 + (kc + 3) * BK);
            CP_COMMIT();
        }

        const uint32_t base = sbase + s * STAGE;
        #pragma unroll
        for (int ks = 0; ks < 2; ++ks) {
            uint32_t ah[2][4], al[2][4], bb[4][2];
            #pragma unroll
            for (int n2 = 0; n2 < 2; ++n2)
                ldm_x4(bb[2 * n2][0], bb[2 * n2][1], bb[2 * n2 + 1][0], bb[2 * n2 + 1][1],
                       base + OFF_BW + bOff[n2][ks]);
            #pragma unroll
            for (int mi = 0; mi < 2; ++mi)
                ldm_x4(ah[mi][0], ah[mi][1], ah[mi][2], ah[mi][3],
                       base + aOff[mi][ks]);
            #pragma unroll
            for (int mi = 0; mi < 2; ++mi)
                ldm_x4(al[mi][0], al[mi][1], al[mi][2], al[mi][3],
                       base + OFF_ALO + aOff[mi][ks]);

            #pragma unroll
            for (int mi = 0; mi < 2; ++mi)
                #pragma unroll
                for (int ni = 0; ni < 4; ++ni) {
                    MMA_S8(accH[mi][ni], ah[mi], bb[ni]);
                    MMA_S8(accL[mi][ni], al[mi], bb[ni]);
                }
        }
    }

    // ---- epilogue: combine planes, bias + hardtanh, fused fc2 ----
    const int dg = lane >> 2;
    const int dt = lane & 3;

    float hv[2][4][4];
    #pragma unroll
    for (int mi = 0; mi < 2; ++mi)
        #pragma unroll
        for (int ni = 0; ni < 4; ++ni)
            #pragma unroll
            for (int q = 0; q < 4; ++q) {
                int n = wn * 32 + ni * 8 + 2 * dt + (q & 1);
                float hf = fmaf(256.0f, (float)accH[mi][ni][q], (float)accL[mi][ni][q]);
                float v  = fmaf(hf, INV_S, b1s[n]);
                hv[mi][ni][q] = fminf(1.0f, fmaxf(-1.0f, v));
            }

    #pragma unroll
    for (int o = 0; o < NOUT; ++o) {
        #pragma unroll
        for (int mi = 0; mi < 2; ++mi) {
            float s0 = 0.0f, s1 = 0.0f;
            #pragma unroll
            for (int ni = 0; ni < 4; ++ni) {
                int n0 = wn * 32 + ni * 8 + 2 * dt;
                float w0 = W2s[o * BN + n0];
                float w1 = W2s[o * BN + n0 + 1];
                s0 = fmaf(hv[mi][ni][0], w0, fmaf(hv[mi][ni][1], w1, s0));
                s1 = fmaf(hv[mi][ni][2], w0, fmaf(hv[mi][ni][3], w1, s1));
            }
            s0 += __shfl_xor_sync(0xffffffffu, s0, 1);
            s0 += __shfl_xor_sync(0xffffffffu, s0, 2);
            s1 += __shfl_xor_sync(0xffffffffu, s1, 1);
            s1 += __shfl_xor_sync(0xffffffffu, s1, 2);
            if (dt == 0) {
                int r0 = bm + wm * 32 + mi * 16 + dg;
                atomicAdd(&out[(size_t)r0 * NOUT + o], s0);
                atomicAdd(&out[(size_t)(r0 + 8) * NOUT + o], s1);
            }
        }
    }
}

// ---------------------------------------------------------------- launch
extern "C" void kernel_launch(void* const* d_in, const int* in_sizes, int n_in,
                              void* d_out, int out_size) {
    const float* X  = (const float*)d_in[0];   // [8192, 784]
    const float* W1 = (const float*)d_in[1];   // [4096, 784]
    const float* b1 = (const float*)d_in[2];   // [4096]
    const float* W2 = (const float*)d_in[3];   // [10, 4096]
    const float* b2 = (const float*)d_in[4];   // [10]
    float* out = (float*)d_out;                // [8192, 10]
    (void)in_sizes; (void)n_in; (void)out_size;

    cudaFuncSetAttribute(fused_i8_kernel,
                         cudaFuncAttributeMaxDynamicSharedMemorySize, SMEM_REQ);

    init_out_kernel<<<(BATCH * NOUT + 255) / 256, 256>>>(out, b2);
    conv_x8_kernel<<<(BATCH * (KP8 / 4) + 255) / 256, 256>>>(X);
    conv_w8_kernel<<<(HID * (KP8 / 4) + 255) / 256, 256>>>(W1);

    dim3 grid(HID / BN, BATCH / BM);   // (32, 128) = 4096 CTAs
    fused_i8_kernel<<<grid, 256, SMEM_REQ>>>(b1, W2, out);
}